// round 3
// baseline (speedup 1.0000x reference)
#include <cuda_runtime.h>
#include <cstdint>
#include <cstddef>
#include <cstring>

// Problem constants
static constexpr int BATCH = 2;
static constexpr int S_LEN = 2048;
static constexpr int HEADS = 16;
static constexpr int HDIM  = 64;
static constexpr int EMB   = 1024;   // HEADS * HDIM
static constexpr int MROWS = BATCH * S_LEN;   // 4096

static constexpr size_t OUT_ELEMS  = (size_t)BATCH * S_LEN * EMB;            // 4,194,304
static constexpr size_t ATTN_ELEMS = (size_t)BATCH * HEADS * S_LEN * S_LEN;  // 134,217,728

// Scratch (static device globals — no runtime allocation)
__device__ float g_q [(size_t)BATCH*HEADS*S_LEN*HDIM];   // [B,H,S,Hd]
__device__ float g_k [(size_t)BATCH*HEADS*S_LEN*HDIM];   // [B,H,S,Hd]
__device__ float g_vt[(size_t)BATCH*HEADS*HDIM*S_LEN];   // [B,H,Hd,S]  (V transposed)
__device__ float g_y [(size_t)BATCH*S_LEN*HEADS*HDIM];   // [B,S,H,Hd] == [4096,1024]

enum { MODE_PLAIN = 0, MODE_QK = 1, MODE_VT = 2, MODE_AV = 3 };

// ---------------------------------------------------------------------------
// Packed f32x2 helpers
// ---------------------------------------------------------------------------
__device__ __forceinline__ unsigned long long splat2(float v) {
    float2 t = make_float2(v, v);
    unsigned long long r;
    memcpy(&r, &t, 8);
    return r;
}

__device__ __forceinline__ void ffma2(unsigned long long& d,
                                      unsigned long long a,
                                      unsigned long long b) {
    asm("fma.rn.f32x2 %0, %1, %2, %0;" : "+l"(d) : "l"(a), "l"(b));
}

__device__ __forceinline__ float2 unpack2(unsigned long long v) {
    float2 t;
    memcpy(&t, &v, 8);
    return t;
}

// ---------------------------------------------------------------------------
// GEMM body:  C = alpha * (A @ B^T) + bias   (A: [M,K] row-major, B: [N,K])
// Packed-FFMA2 microkernel: accumulators paired along M; B splatted in smem.
// ---------------------------------------------------------------------------
template<int BM, int BN, int BK, int TM, int TN>
__device__ __forceinline__
void gemm_body(const float* __restrict__ A, const float* __restrict__ B,
               const float* __restrict__ bias, float* __restrict__ C,
               int M, int N, int K, float alpha, int mode, int z)
{
    constexpr int NT = (BM/TM)*(BN/TN);   // 256
    __shared__ __align__(16) float As[BK][BM + 4];
    // Duplicated+permuted B tile: element for tile-col n lives at
    // f(n) = (n%TN)*(BN/TN) + n/TN, stored as float2(b,b).
    __shared__ __align__(16) unsigned long long Bs2[BK][BN + 1];

    const int tid = threadIdx.x;
    const int row0 = blockIdx.y * BM;
    const int col0 = blockIdx.x * BN;
    const int tx = tid % (BN / TN);
    const int ty = tid / (BN / TN);

    unsigned long long acc[TM/2][TN];
#pragma unroll
    for (int i = 0; i < TM/2; i++)
#pragma unroll
        for (int j = 0; j < TN; j++) acc[i][j] = 0ull;

    for (int k0 = 0; k0 < K; k0 += BK) {
        // A tile (BM x BK) -> As[k][m] transposed
#pragma unroll
        for (int l = 0; l < (BM * BK) / (NT * 4); l++) {
            int idx = (tid + l * NT) * 4;
            int r = idx / BK;
            int c = idx % BK;
            float4 v = *reinterpret_cast<const float4*>(A + (size_t)(row0 + r) * K + k0 + c);
            As[c + 0][r] = v.x; As[c + 1][r] = v.y;
            As[c + 2][r] = v.z; As[c + 3][r] = v.w;
        }
        // B tile (BN x BK) -> Bs2[k][f(n)] duplicated pairs
#pragma unroll
        for (int l = 0; l < (BN * BK) / (NT * 4); l++) {
            int idx = (tid + l * NT) * 4;
            int r = idx / BK;                       // tile col n
            int c = idx % BK;                       // k within tile
            int fr = (r % TN) * (BN / TN) + r / TN; // permuted position
            float4 v = *reinterpret_cast<const float4*>(B + (size_t)(col0 + r) * K + k0 + c);
            Bs2[c + 0][fr] = splat2(v.x);
            Bs2[c + 1][fr] = splat2(v.y);
            Bs2[c + 2][fr] = splat2(v.z);
            Bs2[c + 3][fr] = splat2(v.w);
        }
        __syncthreads();

#pragma unroll
        for (int kk = 0; kk < BK; kk++) {
            // A pairs: (a0,a1),(a2,a3),... free via 128-bit loads
            ulonglong2 a01 = *reinterpret_cast<const ulonglong2*>(&As[kk][ty * TM]);
            ulonglong2 a23 = *reinterpret_cast<const ulonglong2*>(&As[kk][ty * TM + 4]);
            unsigned long long ap[TM/2];
            ap[0] = a01.x; ap[1] = a01.y;
            ap[2] = a23.x; ap[3] = a23.y;

            unsigned long long bp[TN];
#pragma unroll
            for (int j = 0; j < TN; j++)
                bp[j] = Bs2[kk][j * (BN / TN) + tx];

#pragma unroll
            for (int i = 0; i < TM/2; i++)
#pragma unroll
                for (int j = 0; j < TN; j++)
                    ffma2(acc[i][j], ap[i], bp[j]);
        }
        __syncthreads();
    }

    // Epilogue
#pragma unroll
    for (int p = 0; p < TM/2; p++) {
#pragma unroll
        for (int j = 0; j < TN; j++) {
            float2 v2 = unpack2(acc[p][j]);
            const int n = col0 + tx * TN + j;
            float bv = bias ? bias[n] : 0.0f;
#pragma unroll
            for (int h2 = 0; h2 < 2; h2++) {
                const int m = row0 + ty * TM + 2 * p + h2;
                float v = (h2 == 0 ? v2.x : v2.y) * alpha + bv;

                size_t dst;
                if (mode == MODE_PLAIN) {
                    dst = (size_t)m * N + n;
                } else if (mode == MODE_QK) {
                    int b = m >> 11, s = m & 2047;
                    int h = n >> 6,  hd = n & 63;
                    dst = (((size_t)(b * HEADS + h) * S_LEN + s) * HDIM) + hd;
                } else if (mode == MODE_VT) {
                    int b = m >> 11, s = m & 2047;
                    int h = n >> 6,  hd = n & 63;
                    dst = (((size_t)(b * HEADS + h) * HDIM + hd) * S_LEN) + s;
                } else { // MODE_AV
                    int b = z >> 4, h = z & 15;
                    dst = (((size_t)(b * S_LEN + m) * HEADS + h) * HDIM) + n;
                }
                C[dst] = v;
            }
        }
    }
}

// Strided batched wrapper (logits / AV / o-proj)
template<int BM, int BN, int BK, int TM, int TN>
__global__ __launch_bounds__((BM/TM)*(BN/TN))
void gemm_kern(const float* __restrict__ A, const float* __restrict__ B,
               const float* __restrict__ bias, float* __restrict__ C,
               int M, int N, int K,
               size_t sA, size_t sB, size_t sC,
               float alpha, int mode)
{
    const int z = blockIdx.z;
    gemm_body<BM,BN,BK,TM,TN>(A + (size_t)z * sA, B + (size_t)z * sB,
                              bias, C + (size_t)z * sC, M, N, K, alpha, mode, z);
}

// One launch for all three input projections (z selects q/k/v)
struct Proj3 {
    const float* A[3];
    const float* W[3];
    const float* bias[3];
    float*       C[3];
    int          mode[3];
};

template<int BM, int BN, int BK, int TM, int TN>
__global__ __launch_bounds__((BM/TM)*(BN/TN))
void proj3_kern(Proj3 P, int M, int N, int K)
{
    const int z = blockIdx.z;
    gemm_body<BM,BN,BK,TM,TN>(P.A[z], P.W[z], P.bias[z], P.C[z],
                              M, N, K, 1.0f, P.mode[z], z);
}

// ---------------------------------------------------------------------------
// In-place row softmax over rows of length 2048 (one block per row).
// ---------------------------------------------------------------------------
__global__ __launch_bounds__(256)
void softmax_rows(float* __restrict__ attn)
{
    float* row = attn + (size_t)blockIdx.x * S_LEN;
    const int t = threadIdx.x;

    float4 v0 = reinterpret_cast<float4*>(row)[t];
    float4 v1 = reinterpret_cast<float4*>(row)[t + 256];

    float m = fmaxf(fmaxf(fmaxf(v0.x, v0.y), fmaxf(v0.z, v0.w)),
                    fmaxf(fmaxf(v1.x, v1.y), fmaxf(v1.z, v1.w)));

    __shared__ float red[256];
    red[t] = m; __syncthreads();
#pragma unroll
    for (int s = 128; s > 0; s >>= 1) {
        if (t < s) red[t] = fmaxf(red[t], red[t + s]);
        __syncthreads();
    }
    const float M = red[0];
    __syncthreads();

    v0.x = __expf(v0.x - M); v0.y = __expf(v0.y - M);
    v0.z = __expf(v0.z - M); v0.w = __expf(v0.w - M);
    v1.x = __expf(v1.x - M); v1.y = __expf(v1.y - M);
    v1.z = __expf(v1.z - M); v1.w = __expf(v1.w - M);

    float s8 = (v0.x + v0.y + v0.z + v0.w) + (v1.x + v1.y + v1.z + v1.w);
    red[t] = s8; __syncthreads();
#pragma unroll
    for (int s = 128; s > 0; s >>= 1) {
        if (t < s) red[t] += red[t + s];
        __syncthreads();
    }
    const float inv = 1.0f / red[0];

    v0.x *= inv; v0.y *= inv; v0.z *= inv; v0.w *= inv;
    v1.x *= inv; v1.y *= inv; v1.z *= inv; v1.w *= inv;
    reinterpret_cast<float4*>(row)[t]       = v0;
    reinterpret_cast<float4*>(row)[t + 256] = v1;
}

// ---------------------------------------------------------------------------
// Launch
// ---------------------------------------------------------------------------
extern "C" void kernel_launch(void* const* d_in, const int* in_sizes, int n_in,
                              void* d_out, int out_size)
{
    const float* query = (const float*)d_in[0];
    const float* key_i = (const float*)d_in[1];
    const float* value = (const float*)d_in[2];
    const float* q_w   = (const float*)d_in[3];
    const float* q_b   = (const float*)d_in[4];
    const float* k_w   = (const float*)d_in[5];
    const float* k_b   = (const float*)d_in[6];
    const float* v_w   = (const float*)d_in[7];
    const float* v_b   = (const float*)d_in[8];
    const float* o_w   = (const float*)d_in[9];
    const float* o_b   = (const float*)d_in[10];

    float* out  = (float*)d_out;
    float* attn = out + OUT_ELEMS;   // attention occupies the tail of d_out

    float *qp, *kp, *vtp, *yp;
    cudaGetSymbolAddress((void**)&qp,  g_q);
    cudaGetSymbolAddress((void**)&kp,  g_k);
    cudaGetSymbolAddress((void**)&vtp, g_vt);
    cudaGetSymbolAddress((void**)&yp,  g_y);

    const dim3 blk(256);

    // 1) In-projections: one batched launch (z = q, k, v)
    {
        Proj3 P;
        P.A[0] = query; P.W[0] = q_w; P.bias[0] = q_b; P.C[0] = qp;  P.mode[0] = MODE_QK;
        P.A[1] = key_i; P.W[1] = k_w; P.bias[1] = k_b; P.C[1] = kp;  P.mode[1] = MODE_QK;
        P.A[2] = value; P.W[2] = v_w; P.bias[2] = v_b; P.C[2] = vtp; P.mode[2] = MODE_VT;
        dim3 grid(EMB / 128, MROWS / 128, 3);
        proj3_kern<128,128,16,8,8><<<grid, blk>>>(P, MROWS, EMB, EMB);
    }

    // 2) Logits: per (b,h)  Q[2048,64] @ K[2048,64]^T * (1/8) -> attn region
    {
        dim3 grid(S_LEN / 128, S_LEN / 128, BATCH * HEADS);
        gemm_kern<128,128,16,8,8><<<grid, blk>>>(qp, kp, nullptr, attn,
            S_LEN, S_LEN, HDIM,
            (size_t)S_LEN * HDIM, (size_t)S_LEN * HDIM, (size_t)S_LEN * S_LEN,
            0.125f, MODE_PLAIN);
    }

    // 3) Row softmax in place on the attention output
    softmax_rows<<<BATCH * HEADS * S_LEN, blk>>>(attn);

    // 4) AV: per (b,h)  A[2048,2048] @ Vt[64,2048]^T -> y [B,S,H,Hd]
    {
        dim3 grid(HDIM / 64, S_LEN / 128, BATCH * HEADS);
        gemm_kern<128,64,16,8,4><<<grid, blk>>>(attn, vtp, nullptr, yp,
            S_LEN, HDIM, S_LEN,
            (size_t)S_LEN * S_LEN, (size_t)HDIM * S_LEN, 0,
            1.0f, MODE_AV);
    }

    // 5) Output projection: y[4096,1024] @ o_w^T + o_b -> out
    {
        dim3 grid(EMB / 128, MROWS / 128, 1);
        gemm_kern<128,128,16,8,8><<<grid, blk>>>(yp, o_w, o_b, out,
            MROWS, EMB, EMB, 0, 0, 0, 1.0f, MODE_PLAIN);
    }

    (void)in_sizes; (void)n_in; (void)out_size;
}

// round 6
// speedup vs baseline: 1.8154x; 1.8154x over previous
#include <cuda_runtime.h>
#include <cuda_bf16.h>
#include <cstdint>
#include <cstddef>
#include <cstring>

// Problem constants
static constexpr int BATCH = 2;
static constexpr int S_LEN = 2048;
static constexpr int HEADS = 16;
static constexpr int HDIM  = 64;
static constexpr int EMB   = 1024;   // HEADS * HDIM
static constexpr int MROWS = BATCH * S_LEN;   // 4096

static constexpr size_t OUT_ELEMS  = (size_t)BATCH * S_LEN * EMB;            // 4,194,304
static constexpr size_t ATTN_ELEMS = (size_t)BATCH * HEADS * S_LEN * S_LEN;  // 134,217,728

// Scratch (static device globals — no runtime allocation)
__device__ __align__(128) float g_q [(size_t)BATCH*HEADS*S_LEN*HDIM];   // [B,H,S,Hd]
__device__ __align__(128) float g_k [(size_t)BATCH*HEADS*S_LEN*HDIM];   // [B,H,S,Hd]
__device__ __align__(128) float g_vt[(size_t)BATCH*HEADS*HDIM*S_LEN];   // [B,H,Hd,S]
__device__ __align__(128) float g_y [(size_t)BATCH*S_LEN*HEADS*HDIM];   // [B,S,H,Hd]

enum { MODE_PLAIN = 0, MODE_QK = 1, MODE_VT = 2, MODE_AV = 3 };

// ---------------------------------------------------------------------------
// bf16 helpers
// ---------------------------------------------------------------------------
__device__ __forceinline__ uint32_t pack_bf2(float x, float y) {
    __nv_bfloat162 t = __floats2bfloat162_rn(x, y);
    uint32_t r; memcpy(&r, &t, 4); return r;
}

__device__ __forceinline__ void mma_bf16(float c[4],
                                         uint32_t a0, uint32_t a1, uint32_t a2, uint32_t a3,
                                         uint32_t b0, uint32_t b1) {
    asm volatile(
        "mma.sync.aligned.m16n8k16.row.col.f32.bf16.bf16.f32 "
        "{%0,%1,%2,%3}, {%4,%5,%6,%7}, {%8,%9}, {%0,%1,%2,%3};"
        : "+f"(c[0]), "+f"(c[1]), "+f"(c[2]), "+f"(c[3])
        : "r"(a0), "r"(a1), "r"(a2), "r"(a3), "r"(b0), "r"(b1));
}

// ---------------------------------------------------------------------------
// Tensor-core GEMM body (bf16x3 split precision):
//   C = alpha * (A @ B^T) + bias,  A: [M,K] row-major, B: [N,K] row-major
//   Each fp32 operand x split as hi=bf16(x), lo=bf16(x-hi);
//   acc += hi*hi + hi*lo + lo*hi   (fp32 accumulate)  -> ~1e-7 relative error.
// ---------------------------------------------------------------------------
template<int BM, int BN, int BK, int NWM, int NWN>
__device__ __forceinline__
void gemm_body(const float* __restrict__ A, const float* __restrict__ B,
               const float* __restrict__ bias, float* __restrict__ C,
               int M, int N, int K, float alpha, int mode, int z)
{
    constexpr int NT  = NWM * NWN * 32;   // threads
    constexpr int WM  = BM / NWM;         // warp tile M
    constexpr int WN  = BN / NWN;         // warp tile N
    constexpr int MT  = WM / 16;          // m16 tiles per warp
    constexpr int NTJ = WN / 8;           // n8 tiles per warp
    constexpr int LDS = BK + 8;           // padded smem stride (elements)

    __shared__ __align__(16) __nv_bfloat16 Ah[BM * LDS];
    __shared__ __align__(16) __nv_bfloat16 Al[BM * LDS];
    __shared__ __align__(16) __nv_bfloat16 Bh[BN * LDS];
    __shared__ __align__(16) __nv_bfloat16 Bl[BN * LDS];

    const int tid   = threadIdx.x;
    const int warp  = tid >> 5;
    const int lane  = tid & 31;
    const int g     = lane >> 2;     // 0..7
    const int t2    = lane & 3;      // 0..3
    const int wm    = warp / NWN;
    const int wn    = warp % NWN;
    const int m_base = wm * WM;
    const int n_base = wn * WN;

    const int row0 = blockIdx.y * BM;
    const int col0 = blockIdx.x * BN;

    float acc[MT][NTJ][4];
#pragma unroll
    for (int i = 0; i < MT; i++)
#pragma unroll
        for (int j = 0; j < NTJ; j++)
#pragma unroll
            for (int r = 0; r < 4; r++) acc[i][j][r] = 0.0f;

    for (int k0 = 0; k0 < K; k0 += BK) {
        // ---- stage A tile [BM][BK]: fp32 -> (hi, lo) bf16 ----
#pragma unroll
        for (int l = 0; l < (BM * BK) / (4 * NT); l++) {
            int idx = tid + l * NT;                 // float4 index
            int r   = idx / (BK / 4);
            int c4  = idx % (BK / 4);
            float4 v = *reinterpret_cast<const float4*>(A + (size_t)(row0 + r) * K + k0 + c4 * 4);
            float h0 = __bfloat162float(__float2bfloat16_rn(v.x));
            float h1 = __bfloat162float(__float2bfloat16_rn(v.y));
            float h2 = __bfloat162float(__float2bfloat16_rn(v.z));
            float h3 = __bfloat162float(__float2bfloat16_rn(v.w));
            uint2 hw = make_uint2(pack_bf2(v.x, v.y), pack_bf2(v.z, v.w));
            uint2 lw = make_uint2(pack_bf2(v.x - h0, v.y - h1), pack_bf2(v.z - h2, v.w - h3));
            *reinterpret_cast<uint2*>(&Ah[r * LDS + c4 * 4]) = hw;
            *reinterpret_cast<uint2*>(&Al[r * LDS + c4 * 4]) = lw;
        }
        // ---- stage B tile [BN][BK] ----
#pragma unroll
        for (int l = 0; l < (BN * BK) / (4 * NT); l++) {
            int idx = tid + l * NT;
            int r   = idx / (BK / 4);
            int c4  = idx % (BK / 4);
            float4 v = *reinterpret_cast<const float4*>(B + (size_t)(col0 + r) * K + k0 + c4 * 4);
            float h0 = __bfloat162float(__float2bfloat16_rn(v.x));
            float h1 = __bfloat162float(__float2bfloat16_rn(v.y));
            float h2 = __bfloat162float(__float2bfloat16_rn(v.z));
            float h3 = __bfloat162float(__float2bfloat16_rn(v.w));
            uint2 hw = make_uint2(pack_bf2(v.x, v.y), pack_bf2(v.z, v.w));
            uint2 lw = make_uint2(pack_bf2(v.x - h0, v.y - h1), pack_bf2(v.z - h2, v.w - h3));
            *reinterpret_cast<uint2*>(&Bh[r * LDS + c4 * 4]) = hw;
            *reinterpret_cast<uint2*>(&Bl[r * LDS + c4 * 4]) = lw;
        }
        __syncthreads();

        // ---- MMA over BK in k16 steps ----
#pragma unroll
        for (int ks = 0; ks < BK / 16; ks++) {
            const int kk = ks * 16 + t2 * 2;
            uint32_t ah[MT][4], al[MT][4];
#pragma unroll
            for (int i = 0; i < MT; i++) {
                int r0i = (m_base + i * 16 + g) * LDS;
                int r1i = r0i + 8 * LDS;
                memcpy(&ah[i][0], &Ah[r0i + kk],     4);
                memcpy(&ah[i][1], &Ah[r1i + kk],     4);
                memcpy(&ah[i][2], &Ah[r0i + kk + 8], 4);
                memcpy(&ah[i][3], &Ah[r1i + kk + 8], 4);
                memcpy(&al[i][0], &Al[r0i + kk],     4);
                memcpy(&al[i][1], &Al[r1i + kk],     4);
                memcpy(&al[i][2], &Al[r0i + kk + 8], 4);
                memcpy(&al[i][3], &Al[r1i + kk + 8], 4);
            }
#pragma unroll
            for (int j = 0; j < NTJ; j++) {
                int rn = (n_base + j * 8 + g) * LDS;
                uint32_t bh0, bh1, bl0, bl1;
                memcpy(&bh0, &Bh[rn + kk],     4);
                memcpy(&bh1, &Bh[rn + kk + 8], 4);
                memcpy(&bl0, &Bl[rn + kk],     4);
                memcpy(&bl1, &Bl[rn + kk + 8], 4);
#pragma unroll
                for (int i = 0; i < MT; i++) {
                    mma_bf16(acc[i][j], ah[i][0], ah[i][1], ah[i][2], ah[i][3], bh0, bh1);
                    mma_bf16(acc[i][j], ah[i][0], ah[i][1], ah[i][2], ah[i][3], bl0, bl1);
                    mma_bf16(acc[i][j], al[i][0], al[i][1], al[i][2], al[i][3], bh0, bh1);
                }
            }
        }
        __syncthreads();
    }

    // ---- epilogue: scatter per mode ----
#pragma unroll
    for (int i = 0; i < MT; i++) {
#pragma unroll
        for (int j = 0; j < NTJ; j++) {
#pragma unroll
            for (int r = 0; r < 4; r++) {
                const int m = row0 + m_base + i * 16 + g + ((r >= 2) ? 8 : 0);
                const int n = col0 + n_base + j * 8 + t2 * 2 + (r & 1);
                float v = acc[i][j][r] * alpha;
                if (bias) v += bias[n];

                size_t dst;
                if (mode == MODE_PLAIN) {
                    dst = (size_t)m * N + n;
                } else if (mode == MODE_QK) {
                    int b = m >> 11, s = m & 2047;
                    int h = n >> 6,  hd = n & 63;
                    dst = (((size_t)(b * HEADS + h) * S_LEN + s) * HDIM) + hd;
                } else if (mode == MODE_VT) {
                    int b = m >> 11, s = m & 2047;
                    int h = n >> 6,  hd = n & 63;
                    dst = (((size_t)(b * HEADS + h) * HDIM + hd) * S_LEN) + s;
                } else { // MODE_AV: z = b*HEADS + h; m = q row, n = hd
                    int b = z >> 4, h = z & 15;
                    dst = (((size_t)(b * S_LEN + m) * HEADS + h) * HDIM) + n;
                }
                C[dst] = v;
            }
        }
    }
}

// Strided batched wrapper (logits / AV / o-proj)
template<int BM, int BN, int BK, int NWM, int NWN>
__global__ __launch_bounds__(NWM * NWN * 32)
void gemm_kern(const float* __restrict__ A, const float* __restrict__ B,
               const float* __restrict__ bias, float* __restrict__ C,
               int M, int N, int K,
               size_t sA, size_t sB, size_t sC,
               float alpha, int mode)
{
    const int z = blockIdx.z;
    gemm_body<BM,BN,BK,NWM,NWN>(A + (size_t)z * sA, B + (size_t)z * sB,
                                bias, C + (size_t)z * sC, M, N, K, alpha, mode, z);
}

// One launch for all three input projections (z selects q/k/v)
struct Proj3 {
    const float* A[3];
    const float* W[3];
    const float* bias[3];
    float*       C[3];
    int          mode[3];
};

template<int BM, int BN, int BK, int NWM, int NWN>
__global__ __launch_bounds__(NWM * NWN * 32)
void proj3_kern(Proj3 P, int M, int N, int K)
{
    const int z = blockIdx.z;
    gemm_body<BM,BN,BK,NWM,NWN>(P.A[z], P.W[z], P.bias[z], P.C[z],
                                M, N, K, 1.0f, P.mode[z], z);
}

// ---------------------------------------------------------------------------
// In-place row softmax over rows of length 2048 (one block per row).
// ---------------------------------------------------------------------------
__global__ __launch_bounds__(256)
void softmax_rows(float* __restrict__ attn)
{
    float* row = attn + (size_t)blockIdx.x * S_LEN;
    const int t = threadIdx.x;

    float4 v0 = reinterpret_cast<float4*>(row)[t];
    float4 v1 = reinterpret_cast<float4*>(row)[t + 256];

    float m = fmaxf(fmaxf(fmaxf(v0.x, v0.y), fmaxf(v0.z, v0.w)),
                    fmaxf(fmaxf(v1.x, v1.y), fmaxf(v1.z, v1.w)));

    __shared__ float red[256];
    red[t] = m; __syncthreads();
#pragma unroll
    for (int s = 128; s > 0; s >>= 1) {
        if (t < s) red[t] = fmaxf(red[t], red[t + s]);
        __syncthreads();
    }
    const float M = red[0];
    __syncthreads();

    v0.x = __expf(v0.x - M); v0.y = __expf(v0.y - M);
    v0.z = __expf(v0.z - M); v0.w = __expf(v0.w - M);
    v1.x = __expf(v1.x - M); v1.y = __expf(v1.y - M);
    v1.z = __expf(v1.z - M); v1.w = __expf(v1.w - M);

    float s8 = (v0.x + v0.y + v0.z + v0.w) + (v1.x + v1.y + v1.z + v1.w);
    red[t] = s8; __syncthreads();
#pragma unroll
    for (int s = 128; s > 0; s >>= 1) {
        if (t < s) red[t] += red[t + s];
        __syncthreads();
    }
    const float inv = 1.0f / red[0];

    v0.x *= inv; v0.y *= inv; v0.z *= inv; v0.w *= inv;
    v1.x *= inv; v1.y *= inv; v1.z *= inv; v1.w *= inv;
    reinterpret_cast<float4*>(row)[t]       = v0;
    reinterpret_cast<float4*>(row)[t + 256] = v1;
}

// ---------------------------------------------------------------------------
// Launch
// ---------------------------------------------------------------------------
extern "C" void kernel_launch(void* const* d_in, const int* in_sizes, int n_in,
                              void* d_out, int out_size)
{
    const float* query = (const float*)d_in[0];
    const float* key_i = (const float*)d_in[1];
    const float* value = (const float*)d_in[2];
    const float* q_w   = (const float*)d_in[3];
    const float* q_b   = (const float*)d_in[4];
    const float* k_w   = (const float*)d_in[5];
    const float* k_b   = (const float*)d_in[6];
    const float* v_w   = (const float*)d_in[7];
    const float* v_b   = (const float*)d_in[8];
    const float* o_w   = (const float*)d_in[9];
    const float* o_b   = (const float*)d_in[10];

    float* out  = (float*)d_out;
    float* attn = out + OUT_ELEMS;   // attention occupies the tail of d_out

    float *qp, *kp, *vtp, *yp;
    cudaGetSymbolAddress((void**)&qp,  g_q);
    cudaGetSymbolAddress((void**)&kp,  g_k);
    cudaGetSymbolAddress((void**)&vtp, g_vt);
    cudaGetSymbolAddress((void**)&yp,  g_y);

    // 1) In-projections: one batched launch (z = q, k, v)
    {
        Proj3 P;
        P.A[0] = query; P.W[0] = q_w; P.bias[0] = q_b; P.C[0] = qp;  P.mode[0] = MODE_QK;
        P.A[1] = key_i; P.W[1] = k_w; P.bias[1] = k_b; P.C[1] = kp;  P.mode[1] = MODE_QK;
        P.A[2] = value; P.W[2] = v_w; P.bias[2] = v_b; P.C[2] = vtp; P.mode[2] = MODE_VT;
        dim3 grid(EMB / 128, MROWS / 128, 3);
        proj3_kern<128,128,32,2,4><<<grid, 256>>>(P, MROWS, EMB, EMB);
    }

    // 2) Logits: per (b,h)  Q[2048,64] @ K[2048,64]^T * (1/8) -> attn region
    {
        dim3 grid(S_LEN / 128, S_LEN / 128, BATCH * HEADS);
        gemm_kern<128,128,32,2,4><<<grid, 256>>>(qp, kp, nullptr, attn,
            S_LEN, S_LEN, HDIM,
            (size_t)S_LEN * HDIM, (size_t)S_LEN * HDIM, (size_t)S_LEN * S_LEN,
            0.125f, MODE_PLAIN);
    }

    // 3) Row softmax in place on the attention output
    softmax_rows<<<BATCH * HEADS * S_LEN, 256>>>(attn);

    // 4) AV: per (b,h)  A[2048,2048] @ Vt[64,2048]^T -> y [B,S,H,Hd]
    {
        dim3 grid(HDIM / 64, S_LEN / 128, BATCH * HEADS);
        gemm_kern<128,64,32,2,2><<<grid, 128>>>(attn, vtp, nullptr, yp,
            S_LEN, HDIM, S_LEN,
            (size_t)S_LEN * S_LEN, (size_t)HDIM * S_LEN, 0,
            1.0f, MODE_AV);
    }

    // 5) Output projection: y[4096,1024] @ o_w^T + o_b -> out
    {
        dim3 grid(EMB / 128, MROWS / 128, 1);
        gemm_kern<128,128,32,2,4><<<grid, 256>>>(yp, o_w, o_b, out,
            MROWS, EMB, EMB, 0, 0, 0, 1.0f, MODE_PLAIN);
    }

    (void)in_sizes; (void)n_in; (void)out_size;
}

// round 7
// speedup vs baseline: 2.5596x; 1.4100x over previous
#include <cuda_runtime.h>
#include <cuda_bf16.h>
#include <cstdint>
#include <cstddef>
#include <cstring>

// Problem constants
static constexpr int BATCH = 2;
static constexpr int S_LEN = 2048;
static constexpr int HEADS = 16;
static constexpr int HDIM  = 64;
static constexpr int EMB   = 1024;
static constexpr int MROWS = BATCH * S_LEN;   // 4096

static constexpr size_t OUT_ELEMS  = (size_t)BATCH * S_LEN * EMB;            // 4,194,304
static constexpr size_t QKV_ELEMS  = (size_t)BATCH * HEADS * S_LEN * HDIM;   // 4,194,304

// ---------------------------------------------------------------------------
// Persistent packed bf16 hi/lo scratch (static device globals)
// ---------------------------------------------------------------------------
__device__ __align__(128) __nv_bfloat16 g_xqh[OUT_ELEMS], g_xql[OUT_ELEMS];   // packed query input
__device__ __align__(128) __nv_bfloat16 g_xkh[OUT_ELEMS], g_xkl[OUT_ELEMS];   // packed key input
__device__ __align__(128) __nv_bfloat16 g_xvh[OUT_ELEMS], g_xvl[OUT_ELEMS];   // packed value input
__device__ __align__(128) __nv_bfloat16 g_wh[4 * (size_t)EMB * EMB], g_wl[4 * (size_t)EMB * EMB]; // q,k,v,o weights
__device__ __align__(128) __nv_bfloat16 g_qh[QKV_ELEMS], g_ql[QKV_ELEMS];     // Q [B,H,S,Hd] (scaled by 1/8)
__device__ __align__(128) __nv_bfloat16 g_kh[QKV_ELEMS], g_kl[QKV_ELEMS];     // K [B,H,S,Hd]
__device__ __align__(128) __nv_bfloat16 g_vh[QKV_ELEMS], g_vl[QKV_ELEMS];     // V [B,H,S,Hd]
__device__ __align__(128) __nv_bfloat16 g_yh[OUT_ELEMS], g_yl[OUT_ELEMS];     // y [B,S,H,Hd] == [4096,1024]

// ---------------------------------------------------------------------------
// helpers
// ---------------------------------------------------------------------------
__device__ __forceinline__ uint32_t pack_bf2(float x, float y) {
    __nv_bfloat162 t = __floats2bfloat162_rn(x, y);
    uint32_t r; memcpy(&r, &t, 4); return r;
}

__device__ __forceinline__ void mma_bf16(float c[4],
                                         uint32_t a0, uint32_t a1, uint32_t a2, uint32_t a3,
                                         uint32_t b0, uint32_t b1) {
    asm volatile(
        "mma.sync.aligned.m16n8k16.row.col.f32.bf16.bf16.f32 "
        "{%0,%1,%2,%3}, {%4,%5,%6,%7}, {%8,%9}, {%0,%1,%2,%3};"
        : "+f"(c[0]), "+f"(c[1]), "+f"(c[2]), "+f"(c[3])
        : "r"(a0), "r"(a1), "r"(a2), "r"(a3), "r"(b0), "r"(b1));
}

// ---------------------------------------------------------------------------
// Pack kernel: fp32 tensor -> bf16 hi/lo pair arrays (elementwise, float4)
// ---------------------------------------------------------------------------
struct Pack7 {
    const float* s[7];
    __nv_bfloat16 *h[7], *l[7];
    int n4[7];     // number of float4 chunks
};

__global__ __launch_bounds__(256)
void pack_kern(Pack7 P)
{
    const int zi = blockIdx.z;
    const float4* src = reinterpret_cast<const float4*>(P.s[zi]);
    uint2* dh = reinterpret_cast<uint2*>(P.h[zi]);
    uint2* dl = reinterpret_cast<uint2*>(P.l[zi]);
    const int n4 = P.n4[zi];
    for (int i = blockIdx.x * blockDim.x + threadIdx.x; i < n4; i += gridDim.x * blockDim.x) {
        float4 v = src[i];
        float h0 = __bfloat162float(__float2bfloat16_rn(v.x));
        float h1 = __bfloat162float(__float2bfloat16_rn(v.y));
        float h2 = __bfloat162float(__float2bfloat16_rn(v.z));
        float h3 = __bfloat162float(__float2bfloat16_rn(v.w));
        dh[i] = make_uint2(pack_bf2(v.x, v.y), pack_bf2(v.z, v.w));
        dl[i] = make_uint2(pack_bf2(v.x - h0, v.y - h1), pack_bf2(v.z - h2, v.w - h3));
    }
}

// ---------------------------------------------------------------------------
// GEMM body (bf16x3 split precision):  C = A @ B^T (+bias, *alpha)
//   AST: 0 = stage from fp32 with inline split; 1 = copy packed bf16 hi/lo
//   BST: 1 = copy packed bf16 hi/lo; 2 = packed, transposed ([K,BN] source)
//   MODE: 0 = fp32 out (m*N+n), acc*alpha + bias
//         1 = packed out [B,H,S,Hd], (acc+bias)*alpha
//         2 = packed out y [B,S,H,Hd] via z=(b,h), acc (alpha=1, no bias)
// ---------------------------------------------------------------------------
template<int BM, int BN, int BK, int NWM, int NWN, int AST, int BST, int MODE>
__device__ __forceinline__
void gemm_body(const float* __restrict__ Af,
               const __nv_bfloat16* __restrict__ Agh, const __nv_bfloat16* __restrict__ Agl, int lda,
               const __nv_bfloat16* __restrict__ Bgh, const __nv_bfloat16* __restrict__ Bgl, int ldb,
               const float* __restrict__ bias,
               float* __restrict__ Cf, __nv_bfloat16* __restrict__ Ch, __nv_bfloat16* __restrict__ Cl,
               int M, int N, int K, float alpha, int z)
{
    constexpr int NT  = NWM * NWN * 32;
    constexpr int WM  = BM / NWM;
    constexpr int WN  = BN / NWN;
    constexpr int MT  = WM / 16;
    constexpr int NTJ = WN / 8;
    constexpr int LDS = BK + 8;           // x2B = multiple of 16 bytes

    __shared__ __align__(16) __nv_bfloat16 Ah[BM * LDS];
    __shared__ __align__(16) __nv_bfloat16 Al[BM * LDS];
    __shared__ __align__(16) __nv_bfloat16 Bh[BN * LDS];
    __shared__ __align__(16) __nv_bfloat16 Bl[BN * LDS];

    const int tid  = threadIdx.x;
    const int warp = tid >> 5;
    const int lane = tid & 31;
    const int g    = lane >> 2;
    const int t2   = lane & 3;
    const int wm   = warp / NWN;
    const int wn   = warp % NWN;
    const int m_base = wm * WM;
    const int n_base = wn * WN;

    const int row0 = blockIdx.y * BM;
    const int col0 = blockIdx.x * BN;

    float acc[MT][NTJ][4];
#pragma unroll
    for (int i = 0; i < MT; i++)
#pragma unroll
        for (int j = 0; j < NTJ; j++)
#pragma unroll
            for (int r = 0; r < 4; r++) acc[i][j][r] = 0.0f;

    for (int k0 = 0; k0 < K; k0 += BK) {
        // ---- stage A ----
        if constexpr (AST == 0) {
#pragma unroll
            for (int l = 0; l < (BM * BK) / (4 * NT); l++) {
                int idx = tid + l * NT;
                int r   = idx / (BK / 4);
                int c4  = idx % (BK / 4);
                float4 v = *reinterpret_cast<const float4*>(Af + (size_t)(row0 + r) * lda + k0 + c4 * 4);
                float h0 = __bfloat162float(__float2bfloat16_rn(v.x));
                float h1 = __bfloat162float(__float2bfloat16_rn(v.y));
                float h2 = __bfloat162float(__float2bfloat16_rn(v.z));
                float h3 = __bfloat162float(__float2bfloat16_rn(v.w));
                *reinterpret_cast<uint2*>(&Ah[r * LDS + c4 * 4]) =
                    make_uint2(pack_bf2(v.x, v.y), pack_bf2(v.z, v.w));
                *reinterpret_cast<uint2*>(&Al[r * LDS + c4 * 4]) =
                    make_uint2(pack_bf2(v.x - h0, v.y - h1), pack_bf2(v.z - h2, v.w - h3));
            }
        } else {
#pragma unroll
            for (int l = 0; l < (BM * BK) / (8 * NT); l++) {
                int idx = tid + l * NT;
                int r   = idx / (BK / 8);
                int c8  = idx % (BK / 8);
                size_t src = (size_t)(row0 + r) * lda + k0 + c8 * 8;
                *reinterpret_cast<uint4*>(&Ah[r * LDS + c8 * 8]) =
                    *reinterpret_cast<const uint4*>(Agh + src);
                *reinterpret_cast<uint4*>(&Al[r * LDS + c8 * 8]) =
                    *reinterpret_cast<const uint4*>(Agl + src);
            }
        }
        // ---- stage B ----
        if constexpr (BST == 1) {
#pragma unroll
            for (int l = 0; l < (BN * BK) / (8 * NT); l++) {
                int idx = tid + l * NT;
                int r   = idx / (BK / 8);
                int c8  = idx % (BK / 8);
                size_t src = (size_t)(col0 + r) * ldb + k0 + c8 * 8;
                *reinterpret_cast<uint4*>(&Bh[r * LDS + c8 * 8]) =
                    *reinterpret_cast<const uint4*>(Bgh + src);
                *reinterpret_cast<uint4*>(&Bl[r * LDS + c8 * 8]) =
                    *reinterpret_cast<const uint4*>(Bgl + src);
            }
        } else { // BST == 2: source is [K, BN] row-major; smem transposed to [BN][BK]
#pragma unroll
            for (int l = 0; l < (BK * (BN / 8)) / NT; l++) {
                int idx = tid + l * NT;
                int s_i = idx / (BN / 8);
                int h8  = idx % (BN / 8);
                size_t src = (size_t)(k0 + s_i) * ldb + h8 * 8;
                uint4 vh = *reinterpret_cast<const uint4*>(Bgh + src);
                uint4 vl = *reinterpret_cast<const uint4*>(Bgl + src);
                __nv_bfloat16 eh[8], el[8];
                memcpy(eh, &vh, 16);
                memcpy(el, &vl, 16);
#pragma unroll
                for (int e = 0; e < 8; e++) {
                    Bh[(h8 * 8 + e) * LDS + s_i] = eh[e];
                    Bl[(h8 * 8 + e) * LDS + s_i] = el[e];
                }
            }
        }
        __syncthreads();

        // ---- MMA over BK in k16 steps ----
#pragma unroll
        for (int ks = 0; ks < BK / 16; ks++) {
            const int kk = ks * 16 + t2 * 2;
            uint32_t ah[MT][4], al[MT][4];
#pragma unroll
            for (int i = 0; i < MT; i++) {
                int r0i = (m_base + i * 16 + g) * LDS;
                int r1i = r0i + 8 * LDS;
                memcpy(&ah[i][0], &Ah[r0i + kk],     4);
                memcpy(&ah[i][1], &Ah[r1i + kk],     4);
                memcpy(&ah[i][2], &Ah[r0i + kk + 8], 4);
                memcpy(&ah[i][3], &Ah[r1i + kk + 8], 4);
                memcpy(&al[i][0], &Al[r0i + kk],     4);
                memcpy(&al[i][1], &Al[r1i + kk],     4);
                memcpy(&al[i][2], &Al[r0i + kk + 8], 4);
                memcpy(&al[i][3], &Al[r1i + kk + 8], 4);
            }
#pragma unroll
            for (int j = 0; j < NTJ; j++) {
                int rn = (n_base + j * 8 + g) * LDS;
                uint32_t bh0, bh1, bl0, bl1;
                memcpy(&bh0, &Bh[rn + kk],     4);
                memcpy(&bh1, &Bh[rn + kk + 8], 4);
                memcpy(&bl0, &Bl[rn + kk],     4);
                memcpy(&bl1, &Bl[rn + kk + 8], 4);
#pragma unroll
                for (int i = 0; i < MT; i++) {
                    mma_bf16(acc[i][j], ah[i][0], ah[i][1], ah[i][2], ah[i][3], bh0, bh1);
                    mma_bf16(acc[i][j], ah[i][0], ah[i][1], ah[i][2], ah[i][3], bl0, bl1);
                    mma_bf16(acc[i][j], al[i][0], al[i][1], al[i][2], al[i][3], bh0, bh1);
                }
            }
        }
        __syncthreads();
    }

    // ---- epilogue ----
    if constexpr (MODE == 0) {
#pragma unroll
        for (int i = 0; i < MT; i++)
#pragma unroll
            for (int j = 0; j < NTJ; j++)
#pragma unroll
                for (int r = 0; r < 4; r++) {
                    const int m = row0 + m_base + i * 16 + g + ((r >= 2) ? 8 : 0);
                    const int n = col0 + n_base + j * 8 + t2 * 2 + (r & 1);
                    float v = acc[i][j][r] * alpha;
                    if (bias) v += bias[n];
                    Cf[(size_t)m * N + n] = v;
                }
    } else {
#pragma unroll
        for (int i = 0; i < MT; i++)
#pragma unroll
            for (int j = 0; j < NTJ; j++) {
                const int n0 = col0 + n_base + j * 8 + t2 * 2;
                float b0 = bias ? bias[n0]     : 0.0f;
                float b1 = bias ? bias[n0 + 1] : 0.0f;
#pragma unroll
                for (int rp = 0; rp < 2; rp++) {
                    const int m = row0 + m_base + i * 16 + g + 8 * rp;
                    float v0 = (acc[i][j][2 * rp]     + b0) * alpha;
                    float v1 = (acc[i][j][2 * rp + 1] + b1) * alpha;
                    float h0 = __bfloat162float(__float2bfloat16_rn(v0));
                    float h1 = __bfloat162float(__float2bfloat16_rn(v1));
                    uint32_t hw = pack_bf2(v0, v1);
                    uint32_t lw = pack_bf2(v0 - h0, v1 - h1);
                    size_t base;
                    if constexpr (MODE == 1) {
                        int b = m >> 11, s = m & 2047;
                        int h = n0 >> 6, hd = n0 & 63;
                        base = (((size_t)(b * HEADS + h) * S_LEN + s) * HDIM) + hd;
                    } else { // MODE == 2
                        int b = z >> 4, h = z & 15;
                        base = ((size_t)(b * S_LEN + m)) * EMB + h * HDIM + n0;
                    }
                    *reinterpret_cast<uint32_t*>(Ch + base) = hw;
                    *reinterpret_cast<uint32_t*>(Cl + base) = lw;
                }
            }
    }
}

// ---------------------------------------------------------------------------
// Wrapper kernels
// ---------------------------------------------------------------------------
struct ProjArgs {
    const __nv_bfloat16 *axh[3], *axl[3], *bwh[3], *bwl[3];
    const float* bias[3];
    __nv_bfloat16 *ch[3], *cl[3];
    float alpha[3];
};

__global__ __launch_bounds__(256)
void proj3_kern(ProjArgs P)
{
    const int z = blockIdx.z;
    gemm_body<128,128,32,2,4, 1,1,1>(nullptr, P.axh[z], P.axl[z], EMB,
                                     P.bwh[z], P.bwl[z], EMB,
                                     P.bias[z], nullptr, P.ch[z], P.cl[z],
                                     MROWS, EMB, EMB, P.alpha[z], z);
}

__global__ __launch_bounds__(256)
void logits_kern(const __nv_bfloat16* qh, const __nv_bfloat16* ql,
                 const __nv_bfloat16* kh, const __nv_bfloat16* kl,
                 float* attn)
{
    const int z = blockIdx.z;
    const size_t qoff = (size_t)z * S_LEN * HDIM;
    gemm_body<128,128,32,2,4, 1,1,0>(nullptr, qh + qoff, ql + qoff, HDIM,
                                     kh + qoff, kl + qoff, HDIM,
                                     nullptr, attn + (size_t)z * S_LEN * S_LEN, nullptr, nullptr,
                                     S_LEN, S_LEN, HDIM, 1.0f, z);
}

__global__ __launch_bounds__(128)
void av_kern(const float* attn,
             const __nv_bfloat16* vh, const __nv_bfloat16* vl,
             __nv_bfloat16* yh, __nv_bfloat16* yl)
{
    const int z = blockIdx.z;
    const size_t voff = (size_t)z * S_LEN * HDIM;
    gemm_body<128,64,32,2,2, 0,2,2>(attn + (size_t)z * S_LEN * S_LEN, nullptr, nullptr, S_LEN,
                                    vh + voff, vl + voff, HDIM,
                                    nullptr, nullptr, yh, yl,
                                    S_LEN, HDIM, S_LEN, 1.0f, z);
}

__global__ __launch_bounds__(256)
void oproj_kern(const __nv_bfloat16* yh, const __nv_bfloat16* yl,
                const __nv_bfloat16* owh, const __nv_bfloat16* owl,
                const float* ob, float* out)
{
    gemm_body<128,128,32,2,4, 1,1,0>(nullptr, yh, yl, EMB,
                                     owh, owl, EMB,
                                     ob, out, nullptr, nullptr,
                                     MROWS, EMB, EMB, 1.0f, 0);
}

// ---------------------------------------------------------------------------
// In-place row softmax over rows of length 2048 (one block per row).
// ---------------------------------------------------------------------------
__global__ __launch_bounds__(256)
void softmax_rows(float* __restrict__ attn)
{
    float* row = attn + (size_t)blockIdx.x * S_LEN;
    const int t = threadIdx.x;

    float4 v0 = reinterpret_cast<float4*>(row)[t];
    float4 v1 = reinterpret_cast<float4*>(row)[t + 256];

    float m = fmaxf(fmaxf(fmaxf(v0.x, v0.y), fmaxf(v0.z, v0.w)),
                    fmaxf(fmaxf(v1.x, v1.y), fmaxf(v1.z, v1.w)));

    __shared__ float red[256];
    red[t] = m; __syncthreads();
#pragma unroll
    for (int s = 128; s > 0; s >>= 1) {
        if (t < s) red[t] = fmaxf(red[t], red[t + s]);
        __syncthreads();
    }
    const float M = red[0];
    __syncthreads();

    v0.x = __expf(v0.x - M); v0.y = __expf(v0.y - M);
    v0.z = __expf(v0.z - M); v0.w = __expf(v0.w - M);
    v1.x = __expf(v1.x - M); v1.y = __expf(v1.y - M);
    v1.z = __expf(v1.z - M); v1.w = __expf(v1.w - M);

    float s8 = (v0.x + v0.y + v0.z + v0.w) + (v1.x + v1.y + v1.z + v1.w);
    red[t] = s8; __syncthreads();
#pragma unroll
    for (int s = 128; s > 0; s >>= 1) {
        if (t < s) red[t] += red[t + s];
        __syncthreads();
    }
    const float inv = 1.0f / red[0];

    v0.x *= inv; v0.y *= inv; v0.z *= inv; v0.w *= inv;
    v1.x *= inv; v1.y *= inv; v1.z *= inv; v1.w *= inv;
    reinterpret_cast<float4*>(row)[t]       = v0;
    reinterpret_cast<float4*>(row)[t + 256] = v1;
}

// ---------------------------------------------------------------------------
// Launch
// ---------------------------------------------------------------------------
extern "C" void kernel_launch(void* const* d_in, const int* in_sizes, int n_in,
                              void* d_out, int out_size)
{
    const float* query = (const float*)d_in[0];
    const float* key_i = (const float*)d_in[1];
    const float* value = (const float*)d_in[2];
    const float* q_w   = (const float*)d_in[3];
    const float* q_b   = (const float*)d_in[4];
    const float* k_w   = (const float*)d_in[5];
    const float* k_b   = (const float*)d_in[6];
    const float* v_w   = (const float*)d_in[7];
    const float* v_b   = (const float*)d_in[8];
    const float* o_w   = (const float*)d_in[9];
    const float* o_b   = (const float*)d_in[10];

    float* out  = (float*)d_out;
    float* attn = out + OUT_ELEMS;

    __nv_bfloat16 *xqh, *xql, *xkh, *xkl, *xvh, *xvl, *wh, *wl;
    __nv_bfloat16 *qh, *ql, *kh, *kl, *vh, *vl, *yh, *yl;
    cudaGetSymbolAddress((void**)&xqh, g_xqh); cudaGetSymbolAddress((void**)&xql, g_xql);
    cudaGetSymbolAddress((void**)&xkh, g_xkh); cudaGetSymbolAddress((void**)&xkl, g_xkl);
    cudaGetSymbolAddress((void**)&xvh, g_xvh); cudaGetSymbolAddress((void**)&xvl, g_xvl);
    cudaGetSymbolAddress((void**)&wh,  g_wh);  cudaGetSymbolAddress((void**)&wl,  g_wl);
    cudaGetSymbolAddress((void**)&qh,  g_qh);  cudaGetSymbolAddress((void**)&ql,  g_ql);
    cudaGetSymbolAddress((void**)&kh,  g_kh);  cudaGetSymbolAddress((void**)&kl,  g_kl);
    cudaGetSymbolAddress((void**)&vh,  g_vh);  cudaGetSymbolAddress((void**)&vl,  g_vl);
    cudaGetSymbolAddress((void**)&yh,  g_yh);  cudaGetSymbolAddress((void**)&yl,  g_yl);

    const size_t WSZ = (size_t)EMB * EMB;   // 1M elements

    // 0) Pack inputs + weights into bf16 hi/lo
    {
        Pack7 P;
        P.s[0] = query; P.h[0] = xqh; P.l[0] = xql; P.n4[0] = (int)(OUT_ELEMS / 4);
        P.s[1] = key_i; P.h[1] = xkh; P.l[1] = xkl; P.n4[1] = (int)(OUT_ELEMS / 4);
        P.s[2] = value; P.h[2] = xvh; P.l[2] = xvl; P.n4[2] = (int)(OUT_ELEMS / 4);
        P.s[3] = q_w;   P.h[3] = wh + 0 * WSZ; P.l[3] = wl + 0 * WSZ; P.n4[3] = (int)(WSZ / 4);
        P.s[4] = k_w;   P.h[4] = wh + 1 * WSZ; P.l[4] = wl + 1 * WSZ; P.n4[4] = (int)(WSZ / 4);
        P.s[5] = v_w;   P.h[5] = wh + 2 * WSZ; P.l[5] = wl + 2 * WSZ; P.n4[5] = (int)(WSZ / 4);
        P.s[6] = o_w;   P.h[6] = wh + 3 * WSZ; P.l[6] = wl + 3 * WSZ; P.n4[6] = (int)(WSZ / 4);
        pack_kern<<<dim3(512, 1, 7), 256>>>(P);
    }

    // 1) Projections -> packed Q (x 1/8), K, V in [B,H,S,Hd]
    {
        ProjArgs P;
        P.axh[0] = xqh; P.axl[0] = xql; P.bwh[0] = wh + 0 * WSZ; P.bwl[0] = wl + 0 * WSZ;
        P.bias[0] = q_b; P.ch[0] = qh; P.cl[0] = ql; P.alpha[0] = 0.125f;
        P.axh[1] = xkh; P.axl[1] = xkl; P.bwh[1] = wh + 1 * WSZ; P.bwl[1] = wl + 1 * WSZ;
        P.bias[1] = k_b; P.ch[1] = kh; P.cl[1] = kl; P.alpha[1] = 1.0f;
        P.axh[2] = xvh; P.axl[2] = xvl; P.bwh[2] = wh + 2 * WSZ; P.bwl[2] = wl + 2 * WSZ;
        P.bias[2] = v_b; P.ch[2] = vh; P.cl[2] = vl; P.alpha[2] = 1.0f;
        proj3_kern<<<dim3(EMB / 128, MROWS / 128, 3), 256>>>(P);
    }

    // 2) Logits -> attn (fp32, scale already folded into Q)
    logits_kern<<<dim3(S_LEN / 128, S_LEN / 128, BATCH * HEADS), 256>>>(qh, ql, kh, kl, attn);

    // 3) Row softmax in place
    softmax_rows<<<BATCH * HEADS * S_LEN, 256>>>(attn);

    // 4) AV -> packed y [B,S,H,Hd]
    av_kern<<<dim3(1, S_LEN / 128, BATCH * HEADS), 128>>>(attn, vh, vl, yh, yl);

    // 5) Output projection -> out (fp32)
    oproj_kern<<<dim3(EMB / 128, MROWS / 128, 1), 256>>>(yh, yl, wh + 3 * WSZ, wl + 3 * WSZ, o_b, out);

    (void)in_sizes; (void)n_in; (void)out_size;
}